// round 13
// baseline (speedup 1.0000x reference)
#include <cuda_runtime.h>
#include <cstdint>

// x: [2][4][8][8][8][96][96] f32, W: [9][4][4][3][3][3] f32, b: [9][4] f32
// out: [2][4][6][6][8][96][96] f32
#define HW_PLANE 9216
#define KDTILE   2496                // floats per kd sub-tile: 26 rows x 96
#define BUFF     (3 * KDTILE)        // floats per macro buffer (3 kd planes)
typedef unsigned long long u64;

__device__ __forceinline__ u64 pack2(float lo, float hi) {
    u64 r; asm("mov.b64 %0, {%1, %2};" : "=l"(r) : "f"(lo), "f"(hi)); return r;
}
__device__ __forceinline__ void ffma2(u64& a, u64 x, u64 w) {
    asm("fma.rn.f32x2 %0, %1, %2, %0;" : "+l"(a) : "l"(x), "l"(w));
}
__device__ __forceinline__ float2 unpack2(u64 v) {
    float lo, hi; asm("mov.b64 {%0, %1}, %2;" : "=f"(lo), "=f"(hi) : "l"(v));
    return make_float2(lo, hi);
}
__device__ __forceinline__ void mbar_init(uint32_t mbar) {
    asm volatile("mbarrier.init.shared.b64 [%0], 1;" :: "r"(mbar) : "memory");
}
__device__ __forceinline__ void mbar_expect(uint32_t mbar, uint32_t bytes) {
    asm volatile("mbarrier.arrive.expect_tx.shared.b64 _, [%0], %1;"
                 :: "r"(mbar), "r"(bytes) : "memory");
}
__device__ __forceinline__ void mbar_wait(uint32_t mbar, uint32_t parity) {
    asm volatile(
        "{\n\t.reg .pred P;\n\t"
        "WL_%=:\n\t"
        "mbarrier.try_wait.parity.acquire.cta.shared::cta.b64 P, [%0], %1, 0x989680;\n\t"
        "@!P bra WL_%=;\n\t"
        "}" :: "r"(mbar), "r"(parity) : "memory");
}
__device__ __forceinline__ void bulk_g2s(uint32_t dst, const void* src, uint32_t bytes, uint32_t mbar) {
    asm volatile("cp.async.bulk.shared::cta.global.mbarrier::complete_tx::bytes [%0], [%1], %2, [%3];"
                 :: "r"(dst), "l"(src), "r"(bytes), "r"(mbar) : "memory");
}
__device__ __forceinline__ void fence_proxy_async_cta() {
    asm volatile("fence.proxy.async.shared::cta;" ::: "memory");
}

// Winograd F(3,3) along w. Block: 256 thr = 8 warps; warp = 3 out rows x 96 (lane: 3 cols),
// 4 o-chans. 36 macros (ci,i,j) x kd(0..2). Block-shared 26-row tile per kd, double-buffered
// at macro granularity: 3 bulk copies on ONE mbarrier, 1 wait + 1 barrier per macro.
__global__ __launch_bounds__(256, 2)
void conv5d_kernel(const float* __restrict__ x,
                   const float* __restrict__ Wg,
                   const float* __restrict__ bg,
                   float* __restrict__ out)
{
    extern __shared__ __align__(16) float tiles[];     // [2 bufs][3 kd][KDTILE] + 4 pad
    __shared__ __align__(16) float wsh[6480];          // [n(108)][kh(3)][comp(5)][o(4)]
    __shared__ __align__(8) u64 mbars[2];
    __shared__ float mbsh[4];

    const int tid   = threadIdx.x;
    const int warp  = tid >> 5;
    const int lane  = tid & 31;
    const int htile = blockIdx.x % 4;
    const int d     = blockIdx.x / 4;
    const int t     = blockIdx.y;
    const int c     = blockIdx.z % 6;
    const int b     = blockIdx.z / 6;
    const int h0    = htile * 24;

    // ---- stage Winograd-transformed weights
    for (int u = tid; u < 1296; u += 256) {
        int o  = u & 3;
        int kh = (u >> 2) % 3;
        int nn = u / 12;
        int kd = nn % 3;
        int ij = (nn / 3) % 9;
        int ci = nn / 27;
        const float* wp = Wg + ((ij * 4 + o) * 4 + ci) * 27 + kd * 9 + kh * 3;
        float g0 = wp[0], g1 = wp[1], g2 = wp[2];
        float* dst = wsh + (nn * 3 + kh) * 20 + o;
        dst[0]  = 0.5f * g0;
        dst[4]  = 0.5f * (g0 + g1 + g2);
        dst[8]  = (g0 - g1 + g2) * (1.f / 6.f);
        dst[12] = (g0 + 2.f * g1 + 4.f * g2) * (1.f / 6.f);
        dst[16] = g2;
    }
    if (tid < 4) {
        float s = 0.f;
        #pragma unroll
        for (int ij = 0; ij < 9; ij++) s += bg[ij * 4 + tid];
        mbsh[tid] = s * (1.0f / 9.0f);
    }

    const bool v0 = (d >= 1), v2 = (d <= 6);
    const uint32_t nvalid = 1u + (v0 ? 1u : 0u) + (v2 ? 1u : 0u);

    // ---- block bulk-copy geometry: 26 gmem-contiguous rows h0-1 .. h0+24
    const int hstart = h0 - 1;
    const int cstart = (hstart < 0) ? 0 : hstart;
    const int cend   = (h0 + 25 > 96) ? 96 : (h0 + 25);
    const uint32_t cbytes  = (uint32_t)(cend - cstart) * 384u;   // 9600 or 9984
    const uint32_t dstoffB = (uint32_t)(cstart - hstart) * 384u; // 0 or 384
    const int      srcfo   = cstart * 96;

    // ---- static zeroing: invalid h rows (tile rows 0 / 25), invalid kd sub-tiles
    if (hstart < 0) {            // h=-1: local row 0 of each (buf, kd)
        for (int u = tid; u < 576; u += 256) {
            int e = u / 96, w = u - e * 96;          // e = buf*3+kd
            tiles[e * KDTILE + w] = 0.f;             // bufs laid out contiguously
        }
    }
    if (h0 + 25 > 96) {          // h=96: local row 25
        for (int u = tid; u < 576; u += 256) {
            int e = u / 96, w = u - e * 96;
            tiles[e * KDTILE + 25 * 96 + w] = 0.f;
        }
    }
    if (!v0) {                   // d=0: kd0 sub-tile of both bufs stays zero
        for (int u = tid; u < KDTILE; u += 256) {
            tiles[u] = 0.f; tiles[BUFF + u] = 0.f;
        }
    }
    if (!v2) {                   // d=7: kd2 sub-tile of both bufs stays zero
        for (int u = tid; u < KDTILE; u += 256) {
            tiles[2 * KDTILE + u] = 0.f; tiles[BUFF + 2 * KDTILE + u] = 0.f;
        }
    }

    const uint32_t sbt  = (uint32_t)__cvta_generic_to_shared(tiles);
    const uint32_t mbA  = (uint32_t)__cvta_generic_to_shared(&mbars[0]);
    const uint32_t mbB  = mbA + 8;
    if (tid == 0) { mbar_init(mbA); mbar_init(mbB); }
    fence_proxy_async_cta();
    __syncthreads();             // wsh/mbsh/zeroing/mbar init visible

    // ---- issue-side state machine at macro granularity (all threads track bi uniformly)
    const float* bi = x + (size_t)b * (4 * 8 * 8 * 8 * HW_PLANE)
                    + ((size_t)((c * 8 + t) * 8) + (d - 1)) * HW_PLANE;  // dz=d-1 of next issue
    int jj = 0, ii = 0;

    auto issue_macro = [&](int buf) {
        if (tid == 0) {
            uint32_t mb = (buf == 0) ? mbA : mbB;
            mbar_expect(mb, nvalid * cbytes);
            uint32_t dstb = sbt + (uint32_t)buf * (BUFF * 4) + dstoffB;
            if (v0) bulk_g2s(dstb,                  bi + srcfo,                  cbytes, mb);
            bulk_g2s(dstb + KDTILE * 4,             bi + HW_PLANE + srcfo,       cbytes, mb);
            if (v2) bulk_g2s(dstb + 2 * KDTILE * 4, bi + 2 * HW_PLANE + srcfo,   cbytes, mb);
        }
        long step = 8;                       // j++
        jj++;
        if (jj == 3) { jj = 0; ii++; step = 48;            // i++
            if (ii == 3) { ii = 0; step = 368; } }         // ci++
        bi += step * (long)HW_PLANE;
    };

    // Winograd-domain accumulators: 3 output rows x 5 comps x 2 o-pairs
    u64 a01[3][5], a23[3][5];
    #pragma unroll
    for (int py = 0; py < 3; py++) {
        #pragma unroll
        for (int cm = 0; cm < 5; cm++) { a01[py][cm] = 0ull; a23[py][cm] = 0ull; }
    }

    const int  lzoff = (lane == 0) ? 0 : -1;
    const bool lz    = (lane == 0);
    const bool rz    = (lane == 31);

    auto transform_row = [&](const float* rw, u64* T) {
        float am = rw[lzoff];
        float d0 = lz ? 0.f : am;
        float d1 = rw[0], d2 = rw[1], d3 = rw[2];
        float a4 = rw[3];
        float d4 = rz ? 0.f : a4;
        float t3 = d3 - d1;
        float t1 = fmaf(2.f, d1, d2 - d3);
        float t2 = fmaf(3.f, d2, -fmaf(2.f, d1, d3));
        float t0 = fmaf(2.f, d0 - d2, t3);
        float t4 = fmaf(-2.f, t3, d4 - d2);
        T[0] = pack2(t0, t0); T[1] = pack2(t1, t1); T[2] = pack2(t2, t2);
        T[3] = pack2(t3, t3); T[4] = pack2(t4, t4);
    };
    auto fmakh3 = [&](const u64* P0, const u64* P1, const u64* P2, const ulonglong2* wb) {
        #pragma unroll
        for (int cm = 0; cm < 5; cm++) {
            ulonglong2 w2 = wb[cm];
            ffma2(a01[0][cm], P0[cm], w2.x); ffma2(a23[0][cm], P0[cm], w2.y);
            ffma2(a01[1][cm], P1[cm], w2.x); ffma2(a23[1][cm], P1[cm], w2.y);
            ffma2(a01[2][cm], P2[cm], w2.x); ffma2(a23[2][cm], P2[cm], w2.y);
        }
    };
    const ulonglong2* W2 = reinterpret_cast<const ulonglong2*>(wsh);
    auto compute = [&](int n, const float* slot) {
        const ulonglong2* wb = W2 + n * 15;
        const float* tb = slot + (3 * warp) * 96 + 3 * lane;   // local rows 3w..3w+4
        u64 R0[5], R1[5], R2[5];
        transform_row(tb,        R0);
        transform_row(tb + 96,   R1);
        transform_row(tb + 192,  R2);
        fmakh3(R0, R1, R2, wb);          // kh = 0 (rows 0,1,2)
        transform_row(tb + 288,  R0);    // row 3
        fmakh3(R1, R2, R0, wb + 5);      // kh = 1 (rows 1,2,3)
        transform_row(tb + 384,  R1);    // row 4
        fmakh3(R2, R0, R1, wb + 10);     // kh = 2 (rows 2,3,4)
    };

    // prologue: macros 0 -> buf0, 1 -> buf1
    issue_macro(0);
    issue_macro(1);

    uint32_t par[2] = { 0u, 0u };

    #pragma unroll 1
    for (int m = 0; m < 36; m++) {
        const int buf = m & 1;
        mbar_wait(buf == 0 ? mbA : mbB, par[buf]);
        par[buf] ^= 1u;

        const float* base = tiles + buf * BUFF;
        compute(3 * m,     base);
        compute(3 * m + 1, base + KDTILE);
        compute(3 * m + 2, base + 2 * KDTILE);

        __syncthreads();                 // all warps done reading buf before refill
        if (m + 2 < 36) issue_macro(buf);
    }

    // ---- epilogue: inverse Winograd + scale + bias
    const float invn = 1.0f / 9.0f;
    const float mb[4] = { mbsh[0], mbsh[1], mbsh[2], mbsh[3] };
    size_t ob = ((((size_t)(b * 4) * 6 + c) * 6 + t) * 8 + d) * (size_t)HW_PLANE;
    const size_t ostride = (size_t)6 * 6 * 8 * HW_PLANE;

    #pragma unroll
    for (int py = 0; py < 3; py++) {
        int h = h0 + 3 * warp + py;
        size_t rowoff = ob + (size_t)h * 96 + 3 * lane;
        float M[4][5];
        #pragma unroll
        for (int cm = 0; cm < 5; cm++) {
            float2 A = unpack2(a01[py][cm]);
            float2 B = unpack2(a23[py][cm]);
            M[0][cm] = A.x; M[1][cm] = A.y; M[2][cm] = B.x; M[3][cm] = B.y;
        }
        #pragma unroll
        for (int o = 0; o < 4; o++) {
            float y0 = M[o][0] + M[o][1] + M[o][2] + M[o][3];
            float y1 = M[o][1] - M[o][2] + 2.f * M[o][3];
            float y2 = M[o][1] + M[o][2] + fmaf(4.f, M[o][3], M[o][4]);
            float* op = out + rowoff + (size_t)o * ostride;
            op[0] = fmaf(y0, invn, mb[o]);
            op[1] = fmaf(y1, invn, mb[o]);
            op[2] = fmaf(y2, invn, mb[o]);
        }
    }
}

extern "C" void kernel_launch(void* const* d_in, const int* in_sizes, int n_in,
                              void* d_out, int out_size) {
    const float* x  = (const float*)d_in[0];
    const float* Wg = (const float*)d_in[1];
    const float* bg = (const float*)d_in[2];
    float* out = (float*)d_out;

    const int dynsmem = (2 * BUFF + 4) * (int)sizeof(float);   // 2 bufs x 3 kd x 26x96 + pad
    cudaFuncSetAttribute(conv5d_kernel, cudaFuncAttributeMaxDynamicSharedMemorySize, dynsmem);

    dim3 grid(32, 6, 12);   // x: htile(4) + 4*d(8); y: t(6); z: b*6+c(12)
    dim3 block(256);
    conv5d_kernel<<<grid, block, dynsmem>>>(x, Wg, bg, out);
}

// round 14
// speedup vs baseline: 1.5167x; 1.5167x over previous
#include <cuda_runtime.h>
#include <cstdint>

// x: [2][4][8][8][8][96][96] f32, W: [9][4][4][3][3][3] f32, b: [9][4] f32
// out: [2][4][6][6][8][96][96] f32
#define HW_PLANE 9216
#define SLOTF    480                 // floats per slot: 5 rows x 96, unpadded (gmem layout)
typedef unsigned long long u64;

__device__ __forceinline__ u64 pack2(float lo, float hi) {
    u64 r; asm("mov.b64 %0, {%1, %2};" : "=l"(r) : "f"(lo), "f"(hi)); return r;
}
__device__ __forceinline__ void ffma2(u64& a, u64 x, u64 w) {
    asm("fma.rn.f32x2 %0, %1, %2, %0;" : "+l"(a) : "l"(x), "l"(w));
}
__device__ __forceinline__ float2 unpack2(u64 v) {
    float lo, hi; asm("mov.b64 {%0, %1}, %2;" : "=f"(lo), "=f"(hi) : "l"(v));
    return make_float2(lo, hi);
}
__device__ __forceinline__ void mbar_init(uint32_t mbar) {
    asm volatile("mbarrier.init.shared.b64 [%0], 1;" :: "r"(mbar) : "memory");
}
__device__ __forceinline__ void mbar_expect(uint32_t mbar, uint32_t bytes) {
    asm volatile("mbarrier.arrive.expect_tx.shared.b64 _, [%0], %1;"
                 :: "r"(mbar), "r"(bytes) : "memory");
}
__device__ __forceinline__ void mbar_wait(uint32_t mbar, uint32_t parity) {
    asm volatile(
        "{\n\t.reg .pred P;\n\t"
        "WL_%=:\n\t"
        "mbarrier.try_wait.parity.acquire.cta.shared::cta.b64 P, [%0], %1, 0x989680;\n\t"
        "@!P bra WL_%=;\n\t"
        "}" :: "r"(mbar), "r"(parity) : "memory");
}
__device__ __forceinline__ void bulk_g2s(uint32_t dst, const void* src, uint32_t bytes, uint32_t mbar) {
    asm volatile("cp.async.bulk.shared::cta.global.mbarrier::complete_tx::bytes [%0], [%1], %2, [%3];"
                 :: "r"(dst), "l"(src), "r"(bytes), "r"(mbar) : "memory");
}
__device__ __forceinline__ void fence_proxy_async_cta() {
    asm volatile("fence.proxy.async.shared::cta;" ::: "memory");
}

// Winograd F(3,3) along w. Block: 256 thr = 8 warps; warp = 3 out rows x 96 (lane: 3 cols),
// 4 o-chans. 108 iters; per-warp 4 slots (5 rows each) PAIRED on 2 mbarriers: one wait +
// one grouped 2-plane bulk issue per 2 iterations. d-edge handled by zeroed WEIGHTS +
// clamped plane copies (uniform schedule). No LDGSTS, no block barrier in loop. 2 blocks/SM.
__global__ __launch_bounds__(256, 2)
void conv5d_kernel(const float* __restrict__ x,
                   const float* __restrict__ Wg,
                   const float* __restrict__ bg,
                   float* __restrict__ out)
{
    extern __shared__ __align__(16) float tiles[];     // [8 warps][4 slots][SLOTF] + 4 pad
    __shared__ __align__(16) float wsh[6480];          // [n(108)][kh(3)][comp(5)][o(4)]
    __shared__ __align__(8) u64 mbars[8][2];
    __shared__ float mbsh[4];

    const int tid   = threadIdx.x;
    const int warp  = tid >> 5;
    const int lane  = tid & 31;
    const int htile = blockIdx.x % 4;
    const int d     = blockIdx.x / 4;
    const int t     = blockIdx.y;
    const int c     = blockIdx.z % 6;
    const int b     = blockIdx.z / 6;
    const int h0    = htile * 24;

    const bool v0 = (d >= 1), v2 = (d <= 6);

    // ---- stage Winograd-transformed weights; invalid-kd entries forced to ZERO
    for (int u = tid; u < 1296; u += 256) {
        int o  = u & 3;
        int kh = (u >> 2) % 3;
        int nn = u / 12;
        int kd = nn % 3;
        int ij = (nn / 3) % 9;
        int ci = nn / 27;
        const float* wp = Wg + ((ij * 4 + o) * 4 + ci) * 27 + kd * 9 + kh * 3;
        float z = ((kd == 0 && !v0) || (kd == 2 && !v2)) ? 0.f : 1.f;
        float g0 = wp[0] * z, g1 = wp[1] * z, g2 = wp[2] * z;
        float* dst = wsh + (nn * 3 + kh) * 20 + o;
        dst[0]  = 0.5f * g0;
        dst[4]  = 0.5f * (g0 + g1 + g2);
        dst[8]  = (g0 - g1 + g2) * (1.f / 6.f);
        dst[12] = (g0 + 2.f * g1 + 4.f * g2) * (1.f / 6.f);
        dst[16] = g2;
    }
    if (tid < 4) {
        float s = 0.f;
        #pragma unroll
        for (int ij = 0; ij < 9; ij++) s += bg[ij * 4 + tid];
        mbsh[tid] = s * (1.0f / 9.0f);
    }

    float* slab = tiles + warp * (4 * SLOTF);

    // ---- per-warp bulk-copy geometry: 5 gmem-contiguous rows h0+3w-1 .. h0+3w+3
    const int hstart = h0 + 3 * warp - 1;
    const int cstart = (hstart < 0) ? 0 : hstart;
    const int cend   = (hstart + 5 > 96) ? 96 : (hstart + 5);
    const uint32_t cbytes  = (uint32_t)(cend - cstart) * 384u;   // 1920 or 1536
    const uint32_t dstoffB = (uint32_t)(cstart - hstart) * 384u; // 0 or 384
    const int      srcfo   = cstart * 96;

    // ---- static zeroing of h-halo rows (never copied)
    if (hstart < 0) {            // h=-1: row0 of every slot
        #pragma unroll
        for (int s = 0; s < 4; s++) {
            #pragma unroll
            for (int k = 0; k < 3; k++) slab[s * SLOTF + lane * 3 + k] = 0.f;
        }
    }
    if (hstart + 5 > 96) {       // h=96: row4 of every slot
        #pragma unroll
        for (int s = 0; s < 4; s++) {
            #pragma unroll
            for (int k = 0; k < 3; k++) slab[s * SLOTF + 384 + lane * 3 + k] = 0.f;
        }
    }

    const uint32_t sb  = (uint32_t)__cvta_generic_to_shared(slab);
    const uint32_t mbP = (uint32_t)__cvta_generic_to_shared(&mbars[warp][0]);
    const uint32_t mbQ = mbP + 8;
    if (lane == 0) { mbar_init(mbP); mbar_init(mbQ); }
    fence_proxy_async_cta();
    __syncthreads();             // wsh/mbsh/halo-zero/mbar init visible; only block barrier

    // ---- issue-side state machine over (ci,i,j,kd); clamped plane offsets
    const float* bi = x + (size_t)b * (4 * 8 * 8 * 8 * HW_PLANE)
                    + ((size_t)((c * 8 + t) * 8) + (d - 1)) * HW_PLANE;  // dz=d-1 base
    int kd_m = 0, jj = 0, ii = 0;
    const int k0 = v0 ? 0 : 1;       // clamped kd->plane offset
    const int k2 = v2 ? 2 : 1;

    auto next_plane = [&]() -> const float* {
        int ko = (kd_m == 0) ? k0 : ((kd_m == 2) ? k2 : 1);
        const float* p = bi + (size_t)ko * HW_PLANE;
        kd_m++;
        if (kd_m == 3) {
            kd_m = 0;
            long step = 8;                      // j++
            jj++;
            if (jj == 3) { jj = 0; ii++; step = 48;          // i++
                if (ii == 3) { ii = 0; step = 368; } }       // ci++
            bi += step * (long)HW_PLANE;
        }
        return p;
    };
    // issue a slot pair (sA, sA+1) on mbarrier mb: one expect, two bulks
    auto issue_pair = [&](int sA, uint32_t mb) {
        const float* pa = next_plane();
        const float* pb = next_plane();
        if (lane == 0) {
            mbar_expect(mb, 2u * cbytes);
            bulk_g2s(sb + (uint32_t)sA * (SLOTF * 4) + dstoffB,       pa + srcfo, cbytes, mb);
            bulk_g2s(sb + (uint32_t)(sA + 1) * (SLOTF * 4) + dstoffB, pb + srcfo, cbytes, mb);
        }
    };

    // Winograd-domain accumulators: 3 output rows x 5 comps x 2 o-pairs
    u64 a01[3][5], a23[3][5];
    #pragma unroll
    for (int py = 0; py < 3; py++) {
        #pragma unroll
        for (int cm = 0; cm < 5; cm++) { a01[py][cm] = 0ull; a23[py][cm] = 0ull; }
    }

    const int  lzoff = (lane == 0) ? 0 : -1;
    const bool lz    = (lane == 0);
    const bool rz    = (lane == 31);

    auto transform_row = [&](const float* rw, u64* T) {
        float am = rw[lzoff];
        float d0 = lz ? 0.f : am;
        float d1 = rw[0], d2 = rw[1], d3 = rw[2];
        float a4 = rw[3];
        float d4 = rz ? 0.f : a4;
        float t3 = d3 - d1;
        float t1 = fmaf(2.f, d1, d2 - d3);
        float t2 = fmaf(3.f, d2, -fmaf(2.f, d1, d3));
        float t0 = fmaf(2.f, d0 - d2, t3);
        float t4 = fmaf(-2.f, t3, d4 - d2);
        T[0] = pack2(t0, t0); T[1] = pack2(t1, t1); T[2] = pack2(t2, t2);
        T[3] = pack2(t3, t3); T[4] = pack2(t4, t4);
    };
    auto fmakh3 = [&](const u64* P0, const u64* P1, const u64* P2, const ulonglong2* wb) {
        #pragma unroll
        for (int cm = 0; cm < 5; cm++) {
            ulonglong2 w2 = wb[cm];
            ffma2(a01[0][cm], P0[cm], w2.x); ffma2(a23[0][cm], P0[cm], w2.y);
            ffma2(a01[1][cm], P1[cm], w2.x); ffma2(a23[1][cm], P1[cm], w2.y);
            ffma2(a01[2][cm], P2[cm], w2.x); ffma2(a23[2][cm], P2[cm], w2.y);
        }
    };
    const ulonglong2* W2 = reinterpret_cast<const ulonglong2*>(wsh);
    auto compute = [&](int n, const float* slot) {
        const ulonglong2* wb = W2 + n * 15;
        const float* tb = slot + 3 * lane;
        u64 R0[5], R1[5], R2[5];
        transform_row(tb,        R0);
        transform_row(tb + 96,   R1);
        transform_row(tb + 192,  R2);
        fmakh3(R0, R1, R2, wb);          // kh = 0 (rows 0,1,2)
        transform_row(tb + 288,  R0);    // row 3
        fmakh3(R1, R2, R0, wb + 5);      // kh = 1 (rows 1,2,3)
        transform_row(tb + 384,  R1);    // row 4
        fmakh3(R2, R0, R1, wb + 10);     // kh = 2 (rows 2,3,4)
    };

    // prologue: iters 0,1 -> slots 0,1 (mbP); iters 2,3 -> slots 2,3 (mbQ)
    issue_pair(0, mbP);
    issue_pair(2, mbQ);

    uint32_t parP = 0, parQ = 0;

    // 27 rounds x 2 phases; each phase = wait pair, compute 2 iters, re-issue pair
    #pragma unroll 1
    for (int r = 0; r < 27; r++) {
        const int n = 4 * r;

        mbar_wait(mbP, parP); parP ^= 1u;
        compute(n,     slab);
        compute(n + 1, slab + SLOTF);
        if (n + 4 < 108) issue_pair(0, mbP);

        mbar_wait(mbQ, parQ); parQ ^= 1u;
        compute(n + 2, slab + 2 * SLOTF);
        compute(n + 3, slab + 3 * SLOTF);
        if (n + 6 < 108) issue_pair(2, mbQ);
    }

    // ---- epilogue: inverse Winograd + scale + bias
    const float invn = 1.0f / 9.0f;
    const float mb[4] = { mbsh[0], mbsh[1], mbsh[2], mbsh[3] };
    size_t ob = ((((size_t)(b * 4) * 6 + c) * 6 + t) * 8 + d) * (size_t)HW_PLANE;
    const size_t ostride = (size_t)6 * 6 * 8 * HW_PLANE;

    #pragma unroll
    for (int py = 0; py < 3; py++) {
        int h = h0 + 3 * warp + py;
        size_t rowoff = ob + (size_t)h * 96 + 3 * lane;
        float M[4][5];
        #pragma unroll
        for (int cm = 0; cm < 5; cm++) {
            float2 A = unpack2(a01[py][cm]);
            float2 B = unpack2(a23[py][cm]);
            M[0][cm] = A.x; M[1][cm] = A.y; M[2][cm] = B.x; M[3][cm] = B.y;
        }
        #pragma unroll
        for (int o = 0; o < 4; o++) {
            float y0 = M[o][0] + M[o][1] + M[o][2] + M[o][3];
            float y1 = M[o][1] - M[o][2] + 2.f * M[o][3];
            float y2 = M[o][1] + M[o][2] + fmaf(4.f, M[o][3], M[o][4]);
            float* op = out + rowoff + (size_t)o * ostride;
            op[0] = fmaf(y0, invn, mb[o]);
            op[1] = fmaf(y1, invn, mb[o]);
            op[2] = fmaf(y2, invn, mb[o]);
        }
    }
}

extern "C" void kernel_launch(void* const* d_in, const int* in_sizes, int n_in,
                              void* d_out, int out_size) {
    const float* x  = (const float*)d_in[0];
    const float* Wg = (const float*)d_in[1];
    const float* bg = (const float*)d_in[2];
    float* out = (float*)d_out;

    const int dynsmem = (8 * 4 * SLOTF + 4) * (int)sizeof(float);   // 61456 B + pad
    cudaFuncSetAttribute(conv5d_kernel, cudaFuncAttributeMaxDynamicSharedMemorySize, dynsmem);

    dim3 grid(32, 6, 12);   // x: htile(4) + 4*d(8); y: t(6); z: b*6+c(12)
    dim3 block(256);
    conv5d_kernel<<<grid, block, dynsmem>>>(x, Wg, bg, out);
}

// round 15
// speedup vs baseline: 1.6566x; 1.0923x over previous
#include <cuda_runtime.h>
#include <cstdint>

// x: [2][4][8][8][8][96][96] f32, W: [9][4][4][3][3][3] f32, b: [9][4] f32
// out: [2][4][6][6][8][96][96] f32
#define HW_PLANE 9216
#define SLOTF    480                 // floats per slot: 5 rows x 96, unpadded (gmem layout)
typedef unsigned long long u64;

__device__ __forceinline__ u64 pack2(float lo, float hi) {
    u64 r; asm("mov.b64 %0, {%1, %2};" : "=l"(r) : "f"(lo), "f"(hi)); return r;
}
__device__ __forceinline__ void ffma2(u64& a, u64 x, u64 w) {
    asm("fma.rn.f32x2 %0, %1, %2, %0;" : "+l"(a) : "l"(x), "l"(w));
}
__device__ __forceinline__ float2 unpack2(u64 v) {
    float lo, hi; asm("mov.b64 {%0, %1}, %2;" : "=f"(lo), "=f"(hi) : "l"(v));
    return make_float2(lo, hi);
}
__device__ __forceinline__ void mbar_init(uint32_t mbar) {
    asm volatile("mbarrier.init.shared.b64 [%0], 1;" :: "r"(mbar) : "memory");
}
__device__ __forceinline__ void mbar_expect(uint32_t mbar, uint32_t bytes) {
    asm volatile("mbarrier.arrive.expect_tx.shared.b64 _, [%0], %1;"
                 :: "r"(mbar), "r"(bytes) : "memory");
}
__device__ __forceinline__ void mbar_wait(uint32_t mbar, uint32_t parity) {
    asm volatile(
        "{\n\t.reg .pred P;\n\t"
        "WL_%=:\n\t"
        "mbarrier.try_wait.parity.acquire.cta.shared::cta.b64 P, [%0], %1, 0x989680;\n\t"
        "@!P bra WL_%=;\n\t"
        "}" :: "r"(mbar), "r"(parity) : "memory");
}
__device__ __forceinline__ void bulk_g2s(uint32_t dst, const void* src, uint32_t bytes, uint32_t mbar) {
    asm volatile("cp.async.bulk.shared::cta.global.mbarrier::complete_tx::bytes [%0], [%1], %2, [%3];"
                 :: "r"(dst), "l"(src), "r"(bytes), "r"(mbar) : "memory");
}
__device__ __forceinline__ void fence_proxy_async_cta() {
    asm volatile("fence.proxy.async.shared::cta;" ::: "memory");
}

// Winograd F(3,3) along w. Block: 256 thr = 8 warps; warp = 3 out rows x 96 (lane: 3 cols),
// 4 o-chans. 36 macros (ci,i,j; j unrolled) x kd(0..2). Per-warp 5 slots: kd0/kd1 as a
// double-buffered PAIR (slots 0-3, mbarriers A/B) + kd2 single (slot 4, mbarrier C):
// 2 waits per macro instead of 3, all addressing static. d-edges: zeroed weights +
// clamped plane copies (uniform schedule). No LDGSTS, no block barrier in loop. 2 blocks/SM.
__global__ __launch_bounds__(256, 2)
void conv5d_kernel(const float* __restrict__ x,
                   const float* __restrict__ Wg,
                   const float* __restrict__ bg,
                   float* __restrict__ out)
{
    extern __shared__ __align__(16) float tiles[];     // [8 warps][5 slots][SLOTF] + 4 pad
    __shared__ __align__(16) float wsh[6480];          // [n(108)][kh(3)][comp(5)][o(4)]
    __shared__ __align__(8) u64 mbars[8][3];
    __shared__ float mbsh[4];

    const int tid   = threadIdx.x;
    const int warp  = tid >> 5;
    const int lane  = tid & 31;
    const int htile = blockIdx.x % 4;
    const int d     = blockIdx.x / 4;
    const int t     = blockIdx.y;
    const int c     = blockIdx.z % 6;
    const int b     = blockIdx.z / 6;
    const int h0    = htile * 24;

    const bool v0 = (d >= 1), v2 = (d <= 6);

    // ---- stage Winograd-transformed weights; invalid-kd entries forced to ZERO
    for (int u = tid; u < 1296; u += 256) {
        int o  = u & 3;
        int kh = (u >> 2) % 3;
        int nn = u / 12;
        int kd = nn % 3;
        int ij = (nn / 3) % 9;
        int ci = nn / 27;
        const float* wp = Wg + ((ij * 4 + o) * 4 + ci) * 27 + kd * 9 + kh * 3;
        float z = ((kd == 0 && !v0) || (kd == 2 && !v2)) ? 0.f : 1.f;
        float g0 = wp[0] * z, g1 = wp[1] * z, g2 = wp[2] * z;
        float* dst = wsh + (nn * 3 + kh) * 20 + o;
        dst[0]  = 0.5f * g0;
        dst[4]  = 0.5f * (g0 + g1 + g2);
        dst[8]  = (g0 - g1 + g2) * (1.f / 6.f);
        dst[12] = (g0 + 2.f * g1 + 4.f * g2) * (1.f / 6.f);
        dst[16] = g2;
    }
    if (tid < 4) {
        float s = 0.f;
        #pragma unroll
        for (int ij = 0; ij < 9; ij++) s += bg[ij * 4 + tid];
        mbsh[tid] = s * (1.0f / 9.0f);
    }

    float* slab = tiles + warp * (5 * SLOTF);

    // ---- per-warp bulk-copy geometry: 5 gmem-contiguous rows h0+3w-1 .. h0+3w+3
    const int hstart = h0 + 3 * warp - 1;
    const int cstart = (hstart < 0) ? 0 : hstart;
    const int cend   = (hstart + 5 > 96) ? 96 : (hstart + 5);
    const uint32_t cbytes  = (uint32_t)(cend - cstart) * 384u;   // 1920 or 1536
    const uint32_t dstoffB = (uint32_t)(cstart - hstart) * 384u; // 0 or 384
    const int      srcfo   = cstart * 96;

    // ---- static zeroing of h-halo rows (never copied)
    if (hstart < 0) {            // h=-1: row0 of every slot
        #pragma unroll
        for (int s = 0; s < 5; s++) {
            #pragma unroll
            for (int k = 0; k < 3; k++) slab[s * SLOTF + lane * 3 + k] = 0.f;
        }
    }
    if (hstart + 5 > 96) {       // h=96: row4 of every slot
        #pragma unroll
        for (int s = 0; s < 5; s++) {
            #pragma unroll
            for (int k = 0; k < 3; k++) slab[s * SLOTF + 384 + lane * 3 + k] = 0.f;
        }
    }

    const uint32_t sb  = (uint32_t)__cvta_generic_to_shared(slab);
    const uint32_t mbA = (uint32_t)__cvta_generic_to_shared(&mbars[warp][0]);
    const uint32_t mbB = mbA + 8, mbC = mbA + 16;
    if (lane == 0) { mbar_init(mbA); mbar_init(mbB); mbar_init(mbC); }
    fence_proxy_async_cta();
    __syncthreads();             // wsh/mbsh/halo-zero/mbar init visible; only block barrier

    // clamped kd->plane offsets (uniform across loop; invalid kd contributes 0 via weights)
    const size_t k0H = (size_t)(v0 ? 0 : 1) * HW_PLANE;
    const size_t k2H = (size_t)(v2 ? 2 : 1) * HW_PLANE;

    // pair issue: slots (sA, sA+1) <- (kd0, kd1) of macro at base p
    auto issue_pair = [&](uint32_t sA, uint32_t mb, const float* p) {
        if (lane == 0) {
            mbar_expect(mb, 2u * cbytes);
            bulk_g2s(sb + sA * (SLOTF * 4) + dstoffB,           p + k0H + srcfo,     cbytes, mb);
            bulk_g2s(sb + (sA + 1) * (SLOTF * 4) + dstoffB,     p + HW_PLANE + srcfo, cbytes, mb);
        }
    };
    auto issue_single = [&](const float* p) {     // slot 4 <- kd2 of macro at base p
        if (lane == 0) {
            mbar_expect(mbC, cbytes);
            bulk_g2s(sb + 4u * (SLOTF * 4) + dstoffB, p + k2H + srcfo, cbytes, mbC);
        }
    };

    // Winograd-domain accumulators: 3 output rows x 5 comps x 2 o-pairs
    u64 a01[3][5], a23[3][5];
    #pragma unroll
    for (int py = 0; py < 3; py++) {
        #pragma unroll
        for (int cm = 0; cm < 5; cm++) { a01[py][cm] = 0ull; a23[py][cm] = 0ull; }
    }

    const int  lzoff = (lane == 0) ? 0 : -1;
    const bool lz    = (lane == 0);
    const bool rz    = (lane == 31);

    auto transform_row = [&](const float* rw, u64* T) {
        float am = rw[lzoff];
        float d0 = lz ? 0.f : am;
        float d1 = rw[0], d2 = rw[1], d3 = rw[2];
        float a4 = rw[3];
        float d4 = rz ? 0.f : a4;
        float t3 = d3 - d1;
        float t1 = fmaf(2.f, d1, d2 - d3);
        float t2 = fmaf(3.f, d2, -fmaf(2.f, d1, d3));
        float t0 = fmaf(2.f, d0 - d2, t3);
        float t4 = fmaf(-2.f, t3, d4 - d2);
        T[0] = pack2(t0, t0); T[1] = pack2(t1, t1); T[2] = pack2(t2, t2);
        T[3] = pack2(t3, t3); T[4] = pack2(t4, t4);
    };
    auto fmakh3 = [&](const u64* P0, const u64* P1, const u64* P2, const ulonglong2* wb) {
        #pragma unroll
        for (int cm = 0; cm < 5; cm++) {
            ulonglong2 w2 = wb[cm];
            ffma2(a01[0][cm], P0[cm], w2.x); ffma2(a23[0][cm], P0[cm], w2.y);
            ffma2(a01[1][cm], P1[cm], w2.x); ffma2(a23[1][cm], P1[cm], w2.y);
            ffma2(a01[2][cm], P2[cm], w2.x); ffma2(a23[2][cm], P2[cm], w2.y);
        }
    };
    const ulonglong2* W2 = reinterpret_cast<const ulonglong2*>(wsh);
    auto compute = [&](int n, const float* slot) {
        const ulonglong2* wb = W2 + n * 15;
        const float* tb = slot + 3 * lane;
        u64 R0[5], R1[5], R2[5];
        transform_row(tb,        R0);
        transform_row(tb + 96,   R1);
        transform_row(tb + 192,  R2);
        fmakh3(R0, R1, R2, wb);          // kh = 0 (rows 0,1,2)
        transform_row(tb + 288,  R0);    // row 3
        fmakh3(R1, R2, R0, wb + 5);      // kh = 1 (rows 1,2,3)
        transform_row(tb + 384,  R1);    // row 4
        fmakh3(R2, R0, R1, wb + 10);     // kh = 2 (rows 2,3,4)
    };

    const float* bm = x + (size_t)b * (4 * 8 * 8 * 8 * HW_PLANE)
                    + ((size_t)((c * 8 + t) * 8) + (d - 1)) * HW_PLANE;  // macro0 base (dz=d-1)

    // prologue: pair(macro0)->slots0/1 on A; pair(macro1)->slots2/3 on B; kd2(macro0)->slot4 on C
    issue_pair(0, mbA, bm);
    issue_pair(2, mbB, bm + (size_t)8 * HW_PLANE);
    issue_single(bm);

    uint32_t parA = 0, parB = 0, parC = 0;
    uint32_t pb = 0;          // which pair buffer this macro reads: 0 -> slots0/1(A), 1 -> slots2/3(B)
    int n = 0;

    // one macro: wait pair, compute kd0/kd1, re-issue pair for m+2; wait single, compute kd2,
    // re-issue single for m+1. bm2 = base of m+2, bmN = base of m+1. All static selects.
    auto macro_body = [&](const float* bmN, const float* bm2, bool doPair, bool doSingle) {
        uint32_t mbX   = pb ? mbB : mbA;
        uint32_t parX  = pb ? parB : parA;
        const float* sl = slab + (pb ? 2 : 0) * SLOTF;
        mbar_wait(mbX, parX);
        parA ^= (pb ^ 1u); parB ^= pb;
        compute(n,     sl);
        compute(n + 1, sl + SLOTF);
        if (doPair) issue_pair(pb ? 2u : 0u, mbX, bm2);

        mbar_wait(mbC, parC); parC ^= 1u;
        compute(n + 2, slab + 4 * SLOTF);
        if (doSingle) issue_single(bmN);

        pb ^= 1u;
        n += 3;
    };

    #pragma unroll 1
    for (int ci = 0; ci < 4; ci++) {
        #pragma unroll 1
        for (int i = 0; i < 3; i++) {
            const size_t s2 = (size_t)((i < 2) ? 48 : 368) * HW_PLANE;  // step after j=2 macro
            const size_t s8 = (size_t)8 * HW_PLANE;
            const bool lastI = (ci == 3) && (i == 2);
            // j = 0: steps 8, 8
            macro_body(bm + s8, bm + 2 * s8, true, true);
            bm += s8;
            // j = 1: steps 8, s2
            macro_body(bm + s8, bm + s8 + s2, !lastI, true);
            bm += s8;
            // j = 2: steps s2, 8
            macro_body(bm + s2, bm + s2 + s8, !lastI, !lastI);
            bm += s2;
        }
    }

    // ---- epilogue: inverse Winograd + scale + bias
    const float invn = 1.0f / 9.0f;
    const float mb[4] = { mbsh[0], mbsh[1], mbsh[2], mbsh[3] };
    size_t ob = ((((size_t)(b * 4) * 6 + c) * 6 + t) * 8 + d) * (size_t)HW_PLANE;
    const size_t ostride = (size_t)6 * 6 * 8 * HW_PLANE;

    #pragma unroll
    for (int py = 0; py < 3; py++) {
        int h = h0 + 3 * warp + py;
        size_t rowoff = ob + (size_t)h * 96 + 3 * lane;
        float M[4][5];
        #pragma unroll
        for (int cm = 0; cm < 5; cm++) {
            float2 A = unpack2(a01[py][cm]);
            float2 B = unpack2(a23[py][cm]);
            M[0][cm] = A.x; M[1][cm] = A.y; M[2][cm] = B.x; M[3][cm] = B.y;
        }
        #pragma unroll
        for (int o = 0; o < 4; o++) {
            float y0 = M[o][0] + M[o][1] + M[o][2] + M[o][3];
            float y1 = M[o][1] - M[o][2] + 2.f * M[o][3];
            float y2 = M[o][1] + M[o][2] + fmaf(4.f, M[o][3], M[o][4]);
            float* op = out + rowoff + (size_t)o * ostride;
            op[0] = fmaf(y0, invn, mb[o]);
            op[1] = fmaf(y1, invn, mb[o]);
            op[2] = fmaf(y2, invn, mb[o]);
        }
    }
}

extern "C" void kernel_launch(void* const* d_in, const int* in_sizes, int n_in,
                              void* d_out, int out_size) {
    const float* x  = (const float*)d_in[0];
    const float* Wg = (const float*)d_in[1];
    const float* bg = (const float*)d_in[2];
    float* out = (float*)d_out;

    const int dynsmem = (8 * 5 * SLOTF + 4) * (int)sizeof(float);   // 76816 B
    cudaFuncSetAttribute(conv5d_kernel, cudaFuncAttributeMaxDynamicSharedMemorySize, dynsmem);

    dim3 grid(32, 6, 12);   // x: htile(4) + 4*d(8); y: t(6); z: b*6+c(12)
    dim3 block(256);
    conv5d_kernel<<<grid, block, dynsmem>>>(x, Wg, bg, out);
}